// round 11
// baseline (speedup 1.0000x reference)
#include <cuda_runtime.h>
#include <cstdint>

#define N_DATA 131072
#define DVEC   128
#define NSUB   8
#define DSUB   16
#define KCLUS  256
#define NCB    64
#define PPB    256
#define MAXWORK 640            // worst case 512 + 64 partials = 576
#define NLABBLK 256            // label blocks in fused kernel

typedef unsigned long long u64;

// ---------------- device scratch ----------------
__device__ float g_xT[(size_t)N_DATA * DVEC];                       // 67 MB x transposed [n][d]
__device__ float g_ckPack[NCB * NSUB * KCLUS * DSUB];               // 8 MB [cb][s][k][d] (decode)
__device__ __align__(16) u64 g_ckDup[(size_t)NCB * NSUB * KCLUS * DSUB]; // 16 MB lane-duplicated
__device__ __align__(16) u64 g_cn2d[NCB * NSUB * KCLUS];            // dup (-cn/2, -cn/2)
__device__ __align__(16) u64 g_selPair[64 * 32 * 2];                // [dstep][pair][2dims]
__device__ u64   g_ln2[32];
__device__ int   g_lp[N_DATA];        // (posInLabel<<6) | label
__device__ int   g_perm[N_DATA];
__device__ u64   g_codes[N_DATA];
__device__ int   g_hist[NCB];
__device__ int   g_offsets[NCB + 1];
__device__ int4  g_worklist[MAXWORK];
__device__ int   g_nwork;
__device__ int   g_done;

// ---------------- helpers ----------------
__device__ __forceinline__ u64 pk2(float lo, float hi) {
    u64 r; asm("mov.b64 %0, {%1,%2};" : "=l"(r) : "f"(lo), "f"(hi)); return r;
}
__device__ __forceinline__ void unpk2(u64 v, float& lo, float& hi) {
    asm("mov.b64 {%0,%1}, %2;" : "=f"(lo), "=f"(hi) : "l"(v));
}
__device__ __forceinline__ u64 ffma2(u64 a, u64 b, u64 c) {
    u64 d; asm("fma.rn.f32x2 %0, %1, %2, %3;" : "=l"(d) : "l"(a), "l"(b), "l"(c)); return d;
}
__device__ __forceinline__ void cpa16(void* dst, const void* src) {
    unsigned int d = (unsigned int)__cvta_generic_to_shared(dst);
    asm volatile("cp.async.cg.shared.global [%0], [%1], 16;" :: "r"(d), "l"(src));
}
__device__ __forceinline__ void cpa_commit() { asm volatile("cp.async.commit_group;"); }
__device__ __forceinline__ void cpa_wait0()  { asm volatile("cp.async.wait_group 0;"); }

// ---------------- K0: selector pack + state zero (tiny) ----------------
__global__ void k_selpack(const float* __restrict__ sel) {
    __shared__ float cnselS[NCB];
    int tid = threadIdx.x;
    if (tid < NCB) {
        g_hist[tid] = 0;
        float s = 0.f;
        for (int d = 0; d < DVEC; d++) { float v = sel[d * NCB + tid]; s = fmaf(v, v, s); }
        cnselS[tid] = s;
    }
    if (tid == 0) g_done = 0;
    __syncthreads();
    if (tid < 32) g_ln2[tid] = pk2(-0.5f * cnselS[2 * tid], -0.5f * cnselS[2 * tid + 1]);
    for (int i = tid; i < 64 * 32 * 2; i += 256) {
        int ds = i >> 6, r = i & 63, p = r >> 1, j = r & 1, d = 2 * ds + j;
        g_selPair[i] = pk2(sel[d * NCB + 2 * p], sel[d * NCB + 2 * p + 1]);
    }
}

// ---------------- K1: fused labels + xT + rank + codebook pack + scan ----------------
__global__ void __launch_bounds__(256, 2) k_labelpack(const float* __restrict__ x,
                                                      const float* __restrict__ cb) {
    __shared__ union {
        struct { u64 selS[64 * 32 * 2]; u64 ln2S[32]; int hS[NCB]; int baseS[NCB]; } lab;
        struct { float t[DSUB][KCLUS + 1]; } pk;
        struct { int cS[NCB]; int eS[NCB]; } sc;
    } sm;
    __shared__ int isLast;
    int tid = threadIdx.x;
    int bid = blockIdx.x;

    if (bid >= NLABBLK) {
        // ------- codebook pack block -------
        int pb = bid - NLABBLK;                   // 0..511 = cb*NSUB+s
        const float* src = cb + (size_t)pb * DSUB * KCLUS;
        for (int i = tid; i < DSUB * KCLUS; i += 256) sm.pk.t[i >> 8][i & 255] = src[i];
        __syncthreads();
        int k = tid;
        float v[DSUB]; float cn = 0.f;
        #pragma unroll
        for (int d = 0; d < DSUB; d++) { v[d] = sm.pk.t[d][k]; cn = fmaf(v[d], v[d], cn); }
        float4* dst = (float4*)(g_ckPack + ((size_t)pb * KCLUS + k) * DSUB);
        dst[0] = make_float4(v[0], v[1], v[2], v[3]);
        dst[1] = make_float4(v[4], v[5], v[6], v[7]);
        dst[2] = make_float4(v[8], v[9], v[10], v[11]);
        dst[3] = make_float4(v[12], v[13], v[14], v[15]);
        g_cn2d[pb * KCLUS + k] = pk2(-0.5f * cn, -0.5f * cn);
        u64* dp = g_ckDup + ((size_t)pb * KCLUS + k) * DSUB;
        #pragma unroll
        for (int d = 0; d < DSUB; d++)
            dp[d] = pk2(v[d], v[d]);
        return;
    }

    // ------- label block -------
    for (int i = tid; i < 2048; i += 256)
        ((ulonglong2*)sm.lab.selS)[i] = ((const ulonglong2*)g_selPair)[i];
    if (tid < 32) sm.lab.ln2S[tid] = g_ln2[tid];
    if (tid < NCB) sm.lab.hS[tid] = 0;
    __syncthreads();

    int n0 = bid * 512 + tid;
    int n1 = n0 + 256;
    const float* xc0 = x + n0;
    const float* xc1 = x + n1;

    float best0 = -3.4e38f, best1 = -3.4e38f;
    int bl0 = 0, bl1 = 0;

    for (int q = 0; q < 4; q++) {
        u64 acc0[8], acc1[8];
        #pragma unroll
        for (int p = 0; p < 8; p++) { u64 v = sm.lab.ln2S[q * 8 + p]; acc0[p] = v; acc1[p] = v; }

        float xr0[8], xr1[8];
        #pragma unroll
        for (int i = 0; i < 8; i++) xr0[i] = xc0[(size_t)i * N_DATA];
        #pragma unroll
        for (int i = 0; i < 8; i++) xr1[i] = xc1[(size_t)i * N_DATA];

        for (int c = 0; c < 16; c++) {
            float xn0[8], xn1[8];
            if (c < 15) {
                const float* xp0 = xc0 + (size_t)(8 * (c + 1)) * N_DATA;
                const float* xp1 = xc1 + (size_t)(8 * (c + 1)) * N_DATA;
                #pragma unroll
                for (int i = 0; i < 8; i++) xn0[i] = xp0[(size_t)i * N_DATA];
                #pragma unroll
                for (int i = 0; i < 8; i++) xn1[i] = xp1[(size_t)i * N_DATA];
            }

            if (q == 0) {
                float4* d0 = (float4*)(g_xT + (size_t)n0 * DVEC + 8 * c);
                float4* d1 = (float4*)(g_xT + (size_t)n1 * DVEC + 8 * c);
                d0[0] = make_float4(xr0[0], xr0[1], xr0[2], xr0[3]);
                d0[1] = make_float4(xr0[4], xr0[5], xr0[6], xr0[7]);
                d1[0] = make_float4(xr1[0], xr1[1], xr1[2], xr1[3]);
                d1[1] = make_float4(xr1[4], xr1[5], xr1[6], xr1[7]);
            }

            #pragma unroll
            for (int i2 = 0; i2 < 4; i2++) {
                int ds = 4 * c + i2;
                u64 a00 = pk2(xr0[2 * i2], xr0[2 * i2]);
                u64 a01 = pk2(xr0[2 * i2 + 1], xr0[2 * i2 + 1]);
                u64 a10 = pk2(xr1[2 * i2], xr1[2 * i2]);
                u64 a11 = pk2(xr1[2 * i2 + 1], xr1[2 * i2 + 1]);
                const ulonglong2* row = (const ulonglong2*)(sm.lab.selS + ds * 64 + q * 16);
                #pragma unroll
                for (int p = 0; p < 8; p++) {
                    ulonglong2 cc = row[p];
                    acc0[p] = ffma2(a00, cc.x, acc0[p]);
                    acc0[p] = ffma2(a01, cc.y, acc0[p]);
                    acc1[p] = ffma2(a10, cc.x, acc1[p]);
                    acc1[p] = ffma2(a11, cc.y, acc1[p]);
                }
            }
            #pragma unroll
            for (int i = 0; i < 8; i++) { xr0[i] = xn0[i]; xr1[i] = xn1[i]; }
        }

        #pragma unroll
        for (int p = 0; p < 8; p++) {
            int base = 2 * (q * 8 + p);
            float lo, hi;
            unpk2(acc0[p], lo, hi);
            if (lo > best0) { best0 = lo; bl0 = base; }
            if (hi > best0) { best0 = hi; bl0 = base + 1; }
            unpk2(acc1[p], lo, hi);
            if (lo > best1) { best1 = lo; bl1 = base; }
            if (hi > best1) { best1 = hi; bl1 = base + 1; }
        }
    }

    // rank within block, then one global atomic per (block,label)
    int r0 = atomicAdd(&sm.lab.hS[bl0], 1);
    int r1 = atomicAdd(&sm.lab.hS[bl1], 1);
    __syncthreads();
    if (tid < NCB) {
        int c = sm.lab.hS[tid];
        sm.lab.baseS[tid] = (c > 0) ? atomicAdd(&g_hist[tid], c) : 0;
    }
    __syncthreads();
    g_lp[n0] = ((sm.lab.baseS[bl0] + r0) << 6) | bl0;
    g_lp[n1] = ((sm.lab.baseS[bl1] + r1) << 6) | bl1;

    // ------- fused scan: last label block builds offsets + worklist -------
    if (tid == 0) {
        __threadfence();
        int old = atomicAdd(&g_done, 1);
        isLast = (old == NLABBLK - 1);
    }
    __syncthreads();
    if (isLast) {
        int l = tid;
        int c = 0, e = 0;
        if (l < NCB) {
            c = g_hist[l];
            e = (c + PPB - 1) / PPB;
            sm.sc.cS[l] = c; sm.sc.eS[l] = e;
        }
        __syncthreads();
        #pragma unroll
        for (int d = 1; d < NCB; d <<= 1) {
            int vc = 0, ve = 0;
            if (l < NCB && l >= d) { vc = sm.sc.cS[l - d]; ve = sm.sc.eS[l - d]; }
            __syncthreads();
            if (l < NCB) { sm.sc.cS[l] += vc; sm.sc.eS[l] += ve; }
            __syncthreads();
        }
        if (l < NCB) {
            int excl = sm.sc.cS[l] - c;
            int epos = sm.sc.eS[l] - e;
            g_offsets[l] = excl;
            if (l == NCB - 1) { g_offsets[NCB] = sm.sc.cS[l]; g_nwork = sm.sc.eS[l]; }
            for (int i = 0; i < e; i++) {
                int st = i * PPB;
                g_worklist[epos + i] = make_int4(l, excl + st, min(PPB, c - st), 0);
            }
        }
    }
}

// ---------------- K5: scatter — NO atomics ----------------
__global__ void k_scatter() {
    __shared__ int offS[NCB];
    int tid = threadIdx.x;
    if (tid < NCB) offS[tid] = g_offsets[tid];
    __syncthreads();
    int n = blockIdx.x * 256 + tid;
    int lp = g_lp[n];
    g_perm[offS[lp & 63] + (lp >> 6)] = n;
}

// ---------------- K6: main PQ — point-pair lane packing, dup tile ----------------
__global__ void __launch_bounds__(64, 4) k_main() {
    __shared__ __align__(16) u64 ckS[KCLUS * DSUB];   // 32 KB duplicated tile
    __shared__ __align__(16) u64 cn2S[KCLUS];         // 2 KB duplicated -cn/2
    int bid = blockIdx.x;
    if (bid >= g_nwork) return;
    int4 w = g_worklist[bid];
    int label = w.x, start = w.y, cnt = w.z;
    int tid = threadIdx.x;

    const char* tbase = (const char*)(g_ckDup + (size_t)label * NSUB * KCLUS * DSUB);
    const char* cbase = (const char*)(g_cn2d + label * NSUB * KCLUS);

    int base = 4 * tid;
    bool act = (base < cnt);
    bool v0 = act, v1 = (base + 1 < cnt), v2 = (base + 2 < cnt), v3 = (base + 3 < cnt);
    int p0 = g_perm[start + (v0 ? base : 0)];
    int p1 = g_perm[start + (v1 ? base + 1 : 0)];
    int p2 = g_perm[start + (v2 ? base + 2 : 0)];
    int p3 = g_perm[start + (v3 ? base + 3 : 0)];
    u64 codeA = 0, codeB = 0, codeC = 0, codeD = 0;

    for (int s = 0; s < NSUB; s++) {
        // x loads for this s issued before the barrier (overlap with tail of previous compute)
        float4 a0, a1, a2, a3, b0, b1, b2, b3, c0, c1, c2, c3, e0, e1, e2, e3;
        if (act) {
            const float4* xr0 = (const float4*)(g_xT + (size_t)p0 * DVEC + s * DSUB);
            const float4* xr1 = (const float4*)(g_xT + (size_t)p1 * DVEC + s * DSUB);
            const float4* xr2 = (const float4*)(g_xT + (size_t)p2 * DVEC + s * DSUB);
            const float4* xr3 = (const float4*)(g_xT + (size_t)p3 * DVEC + s * DSUB);
            a0 = xr0[0]; a1 = xr0[1]; a2 = xr0[2]; a3 = xr0[3];
            b0 = xr1[0]; b1 = xr1[1]; b2 = xr1[2]; b3 = xr1[3];
            c0 = xr2[0]; c1 = xr2[1]; c2 = xr2[2]; c3 = xr2[3];
            e0 = xr3[0]; e1 = xr3[1]; e2 = xr3[2]; e3 = xr3[3];
        }

        __syncthreads();                 // all warps done with the previous tile
        {   // fill the tile for this s
            char* td = (char*)ckS;
            const char* ts = tbase + (size_t)s * KCLUS * DSUB * 8;
            #pragma unroll
            for (int i = 0; i < 32; i++)
                cpa16(td + (tid + 64 * i) * 16, ts + (tid + 64 * i) * 16);
            const char* cs = cbase + (size_t)s * KCLUS * 8;
            cpa16((char*)cn2S + tid * 16, cs + tid * 16);
            cpa16((char*)cn2S + (tid + 64) * 16, cs + (tid + 64) * 16);
            cpa_commit();
        }

        // build point-pair packed x while the tile streams in (32 u64 = 64 regs)
        u64 xAB[16], xCD[16];
        xAB[0]=pk2(a0.x,b0.x); xAB[1]=pk2(a0.y,b0.y); xAB[2]=pk2(a0.z,b0.z); xAB[3]=pk2(a0.w,b0.w);
        xAB[4]=pk2(a1.x,b1.x); xAB[5]=pk2(a1.y,b1.y); xAB[6]=pk2(a1.z,b1.z); xAB[7]=pk2(a1.w,b1.w);
        xAB[8]=pk2(a2.x,b2.x); xAB[9]=pk2(a2.y,b2.y); xAB[10]=pk2(a2.z,b2.z); xAB[11]=pk2(a2.w,b2.w);
        xAB[12]=pk2(a3.x,b3.x); xAB[13]=pk2(a3.y,b3.y); xAB[14]=pk2(a3.z,b3.z); xAB[15]=pk2(a3.w,b3.w);
        xCD[0]=pk2(c0.x,e0.x); xCD[1]=pk2(c0.y,e0.y); xCD[2]=pk2(c0.z,e0.z); xCD[3]=pk2(c0.w,e0.w);
        xCD[4]=pk2(c1.x,e1.x); xCD[5]=pk2(c1.y,e1.y); xCD[6]=pk2(c1.z,e1.z); xCD[7]=pk2(c1.w,e1.w);
        xCD[8]=pk2(c2.x,e2.x); xCD[9]=pk2(c2.y,e2.y); xCD[10]=pk2(c2.z,e2.z); xCD[11]=pk2(c2.w,e2.w);
        xCD[12]=pk2(c3.x,e3.x); xCD[13]=pk2(c3.y,e3.y); xCD[14]=pk2(c3.z,e3.z); xCD[15]=pk2(c3.w,e3.w);

        cpa_wait0();
        __syncthreads();                 // tile visible to all warps

        float bestA = -3.4e38f, bestB = -3.4e38f, bestC = -3.4e38f, bestD = -3.4e38f;
        int kA = 0, kB = 0, kC = 0, kD = 0;

        #pragma unroll 2
        for (int k = 0; k < KCLUS; k++) {
            const ulonglong2* cr = (const ulonglong2*)(ckS + k * DSUB);
            u64 cn2 = cn2S[k];
            ulonglong2 q0 = cr[0], q1 = cr[1], q2 = cr[2], q3 = cr[3];
            u64 aAB = ffma2(xAB[0], q0.x, cn2);
            u64 aCD = ffma2(xCD[0], q0.x, cn2);
            aAB = ffma2(xAB[1], q0.y, aAB);  aCD = ffma2(xCD[1], q0.y, aCD);
            aAB = ffma2(xAB[2], q1.x, aAB);  aCD = ffma2(xCD[2], q1.x, aCD);
            aAB = ffma2(xAB[3], q1.y, aAB);  aCD = ffma2(xCD[3], q1.y, aCD);
            aAB = ffma2(xAB[4], q2.x, aAB);  aCD = ffma2(xCD[4], q2.x, aCD);
            aAB = ffma2(xAB[5], q2.y, aAB);  aCD = ffma2(xCD[5], q2.y, aCD);
            aAB = ffma2(xAB[6], q3.x, aAB);  aCD = ffma2(xCD[6], q3.x, aCD);
            aAB = ffma2(xAB[7], q3.y, aAB);  aCD = ffma2(xCD[7], q3.y, aCD);
            ulonglong2 q4 = cr[4], q5 = cr[5], q6 = cr[6], q7 = cr[7];
            aAB = ffma2(xAB[8],  q4.x, aAB);  aCD = ffma2(xCD[8],  q4.x, aCD);
            aAB = ffma2(xAB[9],  q4.y, aAB);  aCD = ffma2(xCD[9],  q4.y, aCD);
            aAB = ffma2(xAB[10], q5.x, aAB);  aCD = ffma2(xCD[10], q5.x, aCD);
            aAB = ffma2(xAB[11], q5.y, aAB);  aCD = ffma2(xCD[11], q5.y, aCD);
            aAB = ffma2(xAB[12], q6.x, aAB);  aCD = ffma2(xCD[12], q6.x, aCD);
            aAB = ffma2(xAB[13], q6.y, aAB);  aCD = ffma2(xCD[13], q6.y, aCD);
            aAB = ffma2(xAB[14], q7.x, aAB);  aCD = ffma2(xCD[14], q7.x, aCD);
            aAB = ffma2(xAB[15], q7.y, aAB);  aCD = ffma2(xCD[15], q7.y, aCD);

            float sA, sB, sC, sD;
            unpk2(aAB, sA, sB); unpk2(aCD, sC, sD);
            if (sA > bestA) { bestA = sA; kA = k; }
            if (sB > bestB) { bestB = sB; kB = k; }
            if (sC > bestC) { bestC = sC; kC = k; }
            if (sD > bestD) { bestD = sD; kD = k; }
        }

        codeA |= ((u64)kA) << (8 * s);
        codeB |= ((u64)kB) << (8 * s);
        codeC |= ((u64)kC) << (8 * s);
        codeD |= ((u64)kD) << (8 * s);
    }
    if (v0) g_codes[p0] = codeA;
    if (v1) g_codes[p1] = codeB;
    if (v2) g_codes[p2] = codeC;
    if (v3) g_codes[p3] = codeD;
}

// ---------------- K7: decode — 1 pt/thread, coalesced STG.32 ----------------
__global__ void k_decode(float* __restrict__ out) {
    int n = blockIdx.x * 256 + threadIdx.x;
    int lab = g_lp[n] & 63;
    u64 cd = g_codes[n];
    #pragma unroll
    for (int s = 0; s < NSUB; s++) {
        const float4* c0 = (const float4*)(g_ckPack + ((size_t)(lab * NSUB + s) * KCLUS + (int)((cd >> (8 * s)) & 255)) * DSUB);
        #pragma unroll
        for (int j = 0; j < 4; j++) {
            float4 v = c0[j];
            size_t b = (size_t)(s * DSUB + 4 * j) * N_DATA + n;
            out[b]              = v.x;
            out[b + N_DATA]     = v.y;
            out[b + 2 * N_DATA] = v.z;
            out[b + 3 * N_DATA] = v.w;
        }
    }
}

// ---------------- launch ----------------
extern "C" void kernel_launch(void* const* d_in, const int* in_sizes, int n_in,
                              void* d_out, int out_size) {
    const float* x   = (const float*)d_in[0];
    const float* cb  = (const float*)d_in[1];
    const float* sel = (const float*)d_in[2];
    float* out = (float*)d_out;

    k_selpack<<<1, 256>>>(sel);
    k_labelpack<<<NLABBLK + NCB * NSUB, 256>>>(x, cb);
    k_scatter<<<N_DATA / 256, 256>>>();
    k_main<<<MAXWORK, 64>>>();
    k_decode<<<N_DATA / 256, 256>>>(out);
}